// round 16
// baseline (speedup 1.0000x reference)
#include <cuda_runtime.h>

// Problem constants
#define TT 512
#define DD 16
#define HH 48
#define BTOT 2048
#define NTHREADS 384
#define NCTA 152

typedef unsigned long long ull;

// SMEM byte offsets
#define W1I_B 0                    // [16 k][48 j][16B = I,F,G,O]
#define WR_B  12288                // [48 k][48 j][3 mat][16B]
#define BB1_B 122880               // [48 j][16B = bI,bF,bG,bO]
#define BB2_B 123648
#define H1_B  124416               // [2 buf][16 row][48 x 8B dup]
#define H2_B  136704
#define XD_B  148992               // [2 buf][16 row][16 x 8B dup]
#define SMEM_BYTES 153088

#define HROWD 384                  // dup'd h row bytes
#define HBUFD 6144                 // 16 rows
#define XROWD 128
#define XBUFD 2048

__device__ __forceinline__ float fsig(float x) {
    return __fdividef(1.0f, 1.0f + __expf(-x));
}
__device__ __forceinline__ float ftanh_(float x) {
    return __fdividef(2.0f, 1.0f + __expf(-2.0f * x)) - 1.0f;
}
__device__ __forceinline__ void ffma2(ull& a, ull w, ull h) {
    asm("fma.rn.f32x2 %0, %1, %2, %0;" : "+l"(a) : "l"(w), "l"(h));
}
__device__ __forceinline__ float2 unpk(ull v) {
    float2 r;
    asm("mov.b64 {%0, %1}, %2;" : "=f"(r.x), "=f"(r.y) : "l"(v));
    return r;
}
__device__ __forceinline__ void sts_dup(char* p, float v) {
    ull d;
    asm("mov.b64 %0, {%1, %1};" : "=l"(d) : "f"(v));
    *(ull*)p = d;
}
__device__ __forceinline__ void q_bar(int id) {
    asm volatile("bar.sync %0, 96;" :: "r"(id) : "memory");
}

__global__ void __launch_bounds__(NTHREADS, 1)
lstm2_kernel(const float* __restrict__ x,
             const float* __restrict__ Wih0, const float* __restrict__ Whh0,
             const float* __restrict__ bih0, const float* __restrict__ bhh0,
             const float* __restrict__ Wih1, const float* __restrict__ Whh1,
             const float* __restrict__ bih1, const float* __restrict__ bhh1,
             const float* __restrict__ fcw,  const float* __restrict__ fcb,
             float* __restrict__ out)
{
    extern __shared__ char sm[];
    float* smf = (float*)sm;
    const int tid = threadIdx.x;

    // ---- repack W1I: [16k][48j][4 gates] ----
    for (int i = tid; i < 16*48*4; i += NTHREADS) {
        int g = i & 3, jx = (i >> 2) % 48, k = i / 192;
        smf[(W1I_B >> 2) + i] = Wih0[(g*HH + jx)*DD + k];
    }
    // ---- repack WR: [48k][48j][3 mat][4 gates] (Whh0, Wih1, Whh1) ----
    for (int i = tid; i < 48*48*3*4; i += NTHREADS) {
        int g = i & 3, m = (i >> 2) % 3, jx = (i / 12) % 48, k = i / 576;
        int r = (g*HH + jx)*HH + k;
        smf[(WR_B >> 2) + i] = (m == 0) ? Whh0[r] : (m == 1) ? Wih1[r] : Whh1[r];
    }
    // ---- biases: [48j][4 gates] ----
    for (int i = tid; i < 48*4; i += NTHREADS) {
        int g = i & 3, jx = i >> 2;
        smf[(BB1_B >> 2) + i] = bih0[g*HH + jx] + bhh0[g*HH + jx];
        smf[(BB2_B >> 2) + i] = bih1[g*HH + jx] + bhh1[g*HH + jx];
    }
    // ---- zero h region (H1+H2, both bufs, dup'd) ----
    for (int i = tid; i < (4*HBUFD) >> 2; i += NTHREADS)
        smf[(H1_B >> 2) + i] = 0.f;

    // ---- batch split over 152 CTAs ----
    const int rs = (blockIdx.x * BTOT) / NCTA;
    const int re = ((blockIdx.x + 1) * BTOT) / NCTA;
    const int nb = re - rs;

    // ---- 4 domains x 3 warps; lane: rh=b0, jl=b1..4 ----
    const int w    = tid >> 5;
    const int lane = tid & 31;
    const int q    = w / 3;
    const int wq   = w % 3;
    const int rh   = lane & 1;
    const int j    = wq * 16 + (lane >> 1);
    const int barid = 1 + q;
    const int qtid  = wq * 32 + lane;

    // domain rows
    const int ds  = (q * nb) >> 2;
    const int de  = ((q + 1) * nb) >> 2;
    const int nba = de - ds;                 // 3 or 4
    // thread rows (alias second row when absent -> no divergence)
    const int r0 = ds + rh;
    const int r1 = (rh + 2 < nba) ? (ds + rh + 2) : r0;
    const int hoff0 = r0 * HROWD, hoff1 = r1 * HROWD;
    const int xro0  = r0 * XROWD, xro1  = r1 * XROWD;

    // x staging: 64 threads stage the domain's rows
    const int xrow = ds + (qtid >> 4);
    const int xact = (qtid >> 4) < nba;
    const int xd   = qtid & 15;
    const int xoff = xrow * XROWD + xd * 8;
    const float* xgp = x + (long)(rs + (xact ? (qtid >> 4) + ds : 0)) * (long)(TT*DD) + xd;

    if (xact) sts_dup(sm + XD_B + xoff, xgp[0]);
    __syncthreads();

    const char* pWI = sm + W1I_B + j*16;
    const char* pWR = sm + WR_B + j*48;
    const ulonglong2 b1 = *(const ulonglong2*)(sm + BB1_B + j*16);
    const ulonglong2 b2 = *(const ulonglong2*)(sm + BB2_B + j*16);

    float c1[2] = {0.f, 0.f};
    float c2[2] = {0.f, 0.f};

    for (int t = 0; t <= TT; ++t) {
        const int cur = t & 1, prv = cur ^ 1;

        float xpre = 0.f;
        if (t + 1 < TT && xact)
            xpre = xgp[(t + 1) * DD];

        // accumulators: [row][{I,F} / {G,O}]
        ull a1IF[2], a1GO[2], a2IF[2], a2GO[2];
        #pragma unroll
        for (int ri = 0; ri < 2; ++ri) {
            a1IF[ri] = b1.x; a1GO[ri] = b1.y;
            a2IF[ri] = b2.x; a2GO[ri] = b2.y;
        }

        // ===== layer1 input: x (dup'd) =====
        {
            const char* xb = sm + XD_B + cur*XBUFD;
            #pragma unroll
            for (int kx = 0; kx < 8; ++kx) {
                const ulonglong2 w0 = *(const ulonglong2*)(pWI + (2*kx  )*768);
                const ulonglong2 w1 = *(const ulonglong2*)(pWI + (2*kx+1)*768);
                const ulonglong2 xv0 = *(const ulonglong2*)(xb + xro0 + kx*16);
                const ulonglong2 xv1 = *(const ulonglong2*)(xb + xro1 + kx*16);
                ffma2(a1IF[0], w0.x, xv0.x); ffma2(a1GO[0], w0.y, xv0.x);
                ffma2(a1IF[0], w1.x, xv0.y); ffma2(a1GO[0], w1.y, xv0.y);
                ffma2(a1IF[1], w0.x, xv1.x); ffma2(a1GO[1], w0.y, xv1.x);
                ffma2(a1IF[1], w1.x, xv1.y); ffma2(a1GO[1], w1.y, xv1.y);
            }
        }

        // ===== fused recurrent: W1R@h1[t-1], W2I@h1[t-1], W2R@h2[t-2] =====
        {
            const char* h1b = sm + H1_B + prv*HBUFD;
            const char* h2b = sm + H2_B + cur*HBUFD;
            #pragma unroll 4
            for (int kb = 0; kb < 24; ++kb) {
                const char* wb = pWR + kb*4608;
                const ulonglong2 wA0 = *(const ulonglong2*)(wb);
                const ulonglong2 wB0 = *(const ulonglong2*)(wb + 16);
                const ulonglong2 wC0 = *(const ulonglong2*)(wb + 32);
                const ulonglong2 wA1 = *(const ulonglong2*)(wb + 2304);
                const ulonglong2 wB1 = *(const ulonglong2*)(wb + 2320);
                const ulonglong2 wC1 = *(const ulonglong2*)(wb + 2336);
                const ulonglong2 h1v0 = *(const ulonglong2*)(h1b + hoff0 + kb*16);
                const ulonglong2 h2v0 = *(const ulonglong2*)(h2b + hoff0 + kb*16);
                const ulonglong2 h1v1 = *(const ulonglong2*)(h1b + hoff1 + kb*16);
                const ulonglong2 h2v1 = *(const ulonglong2*)(h2b + hoff1 + kb*16);
                ffma2(a1IF[0], wA0.x, h1v0.x); ffma2(a1GO[0], wA0.y, h1v0.x);
                ffma2(a1IF[0], wA1.x, h1v0.y); ffma2(a1GO[0], wA1.y, h1v0.y);
                ffma2(a2IF[0], wB0.x, h1v0.x); ffma2(a2GO[0], wB0.y, h1v0.x);
                ffma2(a2IF[0], wB1.x, h1v0.y); ffma2(a2GO[0], wB1.y, h1v0.y);
                ffma2(a2IF[0], wC0.x, h2v0.x); ffma2(a2GO[0], wC0.y, h2v0.x);
                ffma2(a2IF[0], wC1.x, h2v0.y); ffma2(a2GO[0], wC1.y, h2v0.y);
                ffma2(a1IF[1], wA0.x, h1v1.x); ffma2(a1GO[1], wA0.y, h1v1.x);
                ffma2(a1IF[1], wA1.x, h1v1.y); ffma2(a1GO[1], wA1.y, h1v1.y);
                ffma2(a2IF[1], wB0.x, h1v1.x); ffma2(a2GO[1], wB0.y, h1v1.x);
                ffma2(a2IF[1], wB1.x, h1v1.y); ffma2(a2GO[1], wB1.y, h1v1.y);
                ffma2(a2IF[1], wC0.x, h2v1.x); ffma2(a2GO[1], wC0.y, h2v1.x);
                ffma2(a2IF[1], wC1.x, h2v1.y); ffma2(a2GO[1], wC1.y, h2v1.y);
            }
        }

        // ===== epilogues: fully thread-local (no shfl, no horizontal add) =====
        char* h1n = sm + H1_B + cur*HBUFD;
        char* h2n = sm + H2_B + prv*HBUFD;
        const int ho[2] = {hoff0, hoff1};

        if (t < TT) {
            #pragma unroll
            for (int ri = 0; ri < 2; ++ri) {
                float2 IF = unpk(a1IF[ri]);
                float2 GO = unpk(a1GO[ri]);
                float iv = fsig(IF.x), fv = fsig(IF.y);
                float gv = ftanh_(GO.x), ov = fsig(GO.y);
                c1[ri] = fmaf(fv, c1[ri], iv * gv);
                sts_dup(h1n + ho[ri] + j*8, ov * ftanh_(c1[ri]));
            }
        }
        if (t > 0) {
            #pragma unroll
            for (int ri = 0; ri < 2; ++ri) {
                float2 IF = unpk(a2IF[ri]);
                float2 GO = unpk(a2GO[ri]);
                float iv = fsig(IF.x), fv = fsig(IF.y);
                float gv = ftanh_(GO.x), ov = fsig(GO.y);
                c2[ri] = fmaf(fv, c2[ri], iv * gv);
                sts_dup(h2n + ho[ri] + j*8, ov * ftanh_(c2[ri]));
            }
        }

        if (t + 1 < TT && xact)
            sts_dup(sm + XD_B + prv*XBUFD + xoff, xpre);

        q_bar(barid);
    }

    __syncthreads();
    // ===== final FC + sigmoid: h2[511] in buf 1 (dup'd rows) =====
    if (tid < nb) {
        const float* h2f = (const float*)(sm + H2_B + HBUFD + tid*HROWD);
        float acc = fcb[0];
        #pragma unroll
        for (int jj = 0; jj < HH; ++jj)
            acc = fmaf(h2f[jj*2], fcw[jj], acc);
        out[rs + tid] = fsig(acc);
    }
}

extern "C" void kernel_launch(void* const* d_in, const int* in_sizes, int n_in,
                              void* d_out, int out_size) {
    (void)in_sizes; (void)n_in; (void)out_size;
    cudaFuncSetAttribute(lstm2_kernel,
                         cudaFuncAttributeMaxDynamicSharedMemorySize, SMEM_BYTES);
    lstm2_kernel<<<NCTA, NTHREADS, SMEM_BYTES>>>(
        (const float*)d_in[0],
        (const float*)d_in[1], (const float*)d_in[2],
        (const float*)d_in[3], (const float*)d_in[4],
        (const float*)d_in[5], (const float*)d_in[6],
        (const float*)d_in[7], (const float*)d_in[8],
        (const float*)d_in[9], (const float*)d_in[10],
        (float*)d_out);
}

// round 17
// speedup vs baseline: 1.5531x; 1.5531x over previous
#include <cuda_runtime.h>

#define TT 512
#define DD 16
#define HH 48
#define BTOT 2048
#define NTHREADS 384
#define NCTA 152

typedef unsigned long long ull;

// SMEM byte offsets
#define W1I_B 0                    // [16 k][48 j][16B {I,F,G,O}]
#define WR_B  12288                // [48 k][3 mat][48 j][16B]
#define BB1_B 122880               // [48 j][16B]
#define BB2_B 123648
#define H1_B  124416               // [2 buf][4 dom][2 pair][12 k4][2 row][16B]
#define H2_B  130560
#define XD_B  136704               // [2 buf][4 dom][2 pair][4 k4][2 row][16B]
#define SMEM_BYTES 138752

#define HBUF 3072                  // per h buffer
#define XBUF 1024

__device__ __forceinline__ float fsig(float x) {
    return __fdividef(1.0f, 1.0f + __expf(-x));
}
__device__ __forceinline__ float ftanh_(float x) {
    return __fdividef(2.0f, 1.0f + __expf(-2.0f * x)) - 1.0f;
}
__device__ __forceinline__ void ffma2(ull& a, ull w, ull h) {
    asm("fma.rn.f32x2 %0, %1, %2, %0;" : "+l"(a) : "l"(w), "l"(h));
}
__device__ __forceinline__ float2 unpk(ull v) {
    float2 r;
    asm("mov.b64 {%0, %1}, %2;" : "=f"(r.x), "=f"(r.y) : "l"(v));
    return r;
}
__device__ __forceinline__ ull dup2(float v) {
    ull d;
    asm("mov.b64 %0, {%1, %1};" : "=l"(d) : "f"(v));
    return d;
}
__device__ __forceinline__ void q_bar(int id) {
    asm volatile("bar.sync %0, 96;" :: "r"(id) : "memory");
}
// h/x address: pair-interleaved so the warp's two rows share a 128B line
__device__ __forceinline__ int haddr(int dom, int rl, int k4) {
    return dom*768 + (rl >> 1)*384 + k4*32 + (rl & 1)*16;
}
__device__ __forceinline__ int xaddr(int dom, int rl, int k4) {
    return dom*256 + (rl >> 1)*128 + k4*32 + (rl & 1)*16;
}

__global__ void __launch_bounds__(NTHREADS, 1)
lstm2_kernel(const float* __restrict__ x,
             const float* __restrict__ Wih0, const float* __restrict__ Whh0,
             const float* __restrict__ bih0, const float* __restrict__ bhh0,
             const float* __restrict__ Wih1, const float* __restrict__ Whh1,
             const float* __restrict__ bih1, const float* __restrict__ bhh1,
             const float* __restrict__ fcw,  const float* __restrict__ fcb,
             float* __restrict__ out)
{
    extern __shared__ char sm[];
    float* smf = (float*)sm;
    const int tid = threadIdx.x;

    // ---- repack W1I: [k][j][4g]  (dst linear = k*192 + j*4 + g) ----
    for (int i = tid; i < 16*48*4; i += NTHREADS) {
        int g = i & 3, jx = (i >> 2) % 48, k = i / 192;
        smf[(W1I_B >> 2) + i] = Wih0[(g*HH + jx)*DD + k];
    }
    // ---- repack WR: [k][mat][j][4g]  (dst = k*576 + m*192 + j*4 + g) ----
    for (int i = tid; i < 48*3*48*4; i += NTHREADS) {
        int g = i & 3, jx = (i >> 2) % 48, m = (i / 192) % 3, k = i / 576;
        int r = (g*HH + jx)*HH + k;
        smf[(WR_B >> 2) + i] = (m == 0) ? Whh0[r] : (m == 1) ? Wih1[r] : Whh1[r];
    }
    // ---- biases: [j][4g] ----
    for (int i = tid; i < 48*4; i += NTHREADS) {
        int g = i & 3, jx = i >> 2;
        smf[(BB1_B >> 2) + i] = bih0[g*HH + jx] + bhh0[g*HH + jx];
        smf[(BB2_B >> 2) + i] = bih1[g*HH + jx] + bhh1[g*HH + jx];
    }
    // ---- zero h buffers ----
    for (int i = tid; i < (4*HBUF) >> 2; i += NTHREADS)
        smf[(H1_B >> 2) + i] = 0.f;

    // ---- batch split over CTAs ----
    const int rs = (blockIdx.x * BTOT) / NCTA;
    const int nb = ((blockIdx.x + 1) * BTOT) / NCTA - rs;

    // ---- 4 domains x 3 warps; lane: rh=b0, jl=b1..4 ----
    const int w    = tid >> 5;
    const int lane = tid & 31;
    const int q    = w / 3;
    const int wq   = w % 3;
    const int rh   = lane & 1;
    const int j    = wq * 16 + (lane >> 1);
    const int barid = 1 + q;
    const int qtid  = wq * 32 + lane;

    const int ds  = (q * nb) >> 2;
    const int nba = (((q + 1) * nb) >> 2) - ds;   // 3 or 4
    const int rl0 = rh;
    const int rl1 = (rh + 2 < nba) ? rh + 2 : rh; // alias if absent

    // x staging: 64 threads per domain stage its rows
    const int xrl  = qtid >> 4;                   // local row 0..3
    const int xact = xrl < nba;
    const int xd   = qtid & 15;
    const int xoff = xaddr(q, xrl, xd >> 2) + (xd & 3)*4;
    const float* xgp = x + (long)(rs + ds + (xact ? xrl : 0)) * (long)(TT*DD) + xd;

    if (xact) *(float*)(sm + XD_B + xoff) = xgp[0];
    __syncthreads();

    const char* pWI = sm + W1I_B + j*16;
    const char* pWR = sm + WR_B + j*16;
    const ulonglong2 b1 = *(const ulonglong2*)(sm + BB1_B + j*16);
    const ulonglong2 b2 = *(const ulonglong2*)(sm + BB2_B + j*16);

    float c1[2] = {0.f, 0.f};
    float c2[2] = {0.f, 0.f};
    // store offsets (scalar float at [row][j])
    const int hst0 = q*768 + (rl0 >> 1)*384 + (j >> 2)*32 + (rl0 & 1)*16 + (j & 3)*4;
    const int hst1 = q*768 + (rl1 >> 1)*384 + (j >> 2)*32 + (rl1 & 1)*16 + (j & 3)*4;

    for (int t = 0; t <= TT; ++t) {
        const int cur = t & 1, prv = cur ^ 1;

        float xpre = 0.f;
        if (t + 1 < TT && xact)
            xpre = xgp[(t + 1) * DD];

        ull a1IF[2], a1GO[2], a2IF[2], a2GO[2];
        #pragma unroll
        for (int ri = 0; ri < 2; ++ri) {
            a1IF[ri] = b1.x; a1GO[ri] = b1.y;
            a2IF[ri] = b2.x; a2GO[ri] = b2.y;
        }

        // ===== layer1 input: x (register-dup operands) =====
        {
            const char* xb = sm + XD_B + cur*XBUF;
            #pragma unroll
            for (int kq = 0; kq < 4; ++kq) {
                const float4 x0 = *(const float4*)(xb + xaddr(q, rl0, kq));
                const float4 x1 = *(const float4*)(xb + xaddr(q, rl1, kq));
                #pragma unroll
                for (int kk = 0; kk < 4; ++kk) {
                    const ulonglong2 wI = *(const ulonglong2*)(pWI + (kq*4 + kk)*768);
                    const float e0 = (kk==0)?x0.x:(kk==1)?x0.y:(kk==2)?x0.z:x0.w;
                    const float e1 = (kk==0)?x1.x:(kk==1)?x1.y:(kk==2)?x1.z:x1.w;
                    const ull d0 = dup2(e0), d1 = dup2(e1);
                    ffma2(a1IF[0], wI.x, d0); ffma2(a1GO[0], wI.y, d0);
                    ffma2(a1IF[1], wI.x, d1); ffma2(a1GO[1], wI.y, d1);
                }
            }
        }

        // ===== fused recurrent: W1R@h1[t-1], W2I@h1[t-1], W2R@h2[t-2] =====
        {
            const char* h1b = sm + H1_B + prv*HBUF;
            const char* h2b = sm + H2_B + cur*HBUF;
            #pragma unroll 3
            for (int kq = 0; kq < 12; ++kq) {
                const float4 h10 = *(const float4*)(h1b + haddr(q, rl0, kq));
                const float4 h11 = *(const float4*)(h1b + haddr(q, rl1, kq));
                const float4 h20 = *(const float4*)(h2b + haddr(q, rl0, kq));
                const float4 h21 = *(const float4*)(h2b + haddr(q, rl1, kq));
                #pragma unroll
                for (int kk = 0; kk < 4; ++kk) {
                    const char* wk = pWR + (kq*4 + kk)*2304;
                    const ulonglong2 wA = *(const ulonglong2*)(wk);
                    const ulonglong2 wB = *(const ulonglong2*)(wk + 768);
                    const ulonglong2 wC = *(const ulonglong2*)(wk + 1536);
                    const float e10 = (kk==0)?h10.x:(kk==1)?h10.y:(kk==2)?h10.z:h10.w;
                    const float e11 = (kk==0)?h11.x:(kk==1)?h11.y:(kk==2)?h11.z:h11.w;
                    const float e20 = (kk==0)?h20.x:(kk==1)?h20.y:(kk==2)?h20.z:h20.w;
                    const float e21 = (kk==0)?h21.x:(kk==1)?h21.y:(kk==2)?h21.z:h21.w;
                    const ull d10 = dup2(e10), d11 = dup2(e11);
                    const ull d20 = dup2(e20), d21 = dup2(e21);
                    ffma2(a1IF[0], wA.x, d10); ffma2(a1GO[0], wA.y, d10);
                    ffma2(a2IF[0], wB.x, d10); ffma2(a2GO[0], wB.y, d10);
                    ffma2(a2IF[0], wC.x, d20); ffma2(a2GO[0], wC.y, d20);
                    ffma2(a1IF[1], wA.x, d11); ffma2(a1GO[1], wA.y, d11);
                    ffma2(a2IF[1], wB.x, d11); ffma2(a2GO[1], wB.y, d11);
                    ffma2(a2IF[1], wC.x, d21); ffma2(a2GO[1], wC.y, d21);
                }
            }
        }

        // ===== thread-local epilogues (no shfl, no horizontal add) =====
        char* h1n = sm + H1_B + cur*HBUF;
        char* h2n = sm + H2_B + prv*HBUF;
        const int hst[2] = {hst0, hst1};

        if (t < TT) {
            #pragma unroll
            for (int ri = 0; ri < 2; ++ri) {
                float2 IF = unpk(a1IF[ri]);
                float2 GO = unpk(a1GO[ri]);
                float iv = fsig(IF.x), fv = fsig(IF.y);
                float gv = ftanh_(GO.x), ov = fsig(GO.y);
                c1[ri] = fmaf(fv, c1[ri], iv * gv);
                *(float*)(h1n + hst[ri]) = ov * ftanh_(c1[ri]);
            }
        }
        if (t > 0) {
            #pragma unroll
            for (int ri = 0; ri < 2; ++ri) {
                float2 IF = unpk(a2IF[ri]);
                float2 GO = unpk(a2GO[ri]);
                float iv = fsig(IF.x), fv = fsig(IF.y);
                float gv = ftanh_(GO.x), ov = fsig(GO.y);
                c2[ri] = fmaf(fv, c2[ri], iv * gv);
                *(float*)(h2n + hst[ri]) = ov * ftanh_(c2[ri]);
            }
        }

        if (t + 1 < TT && xact)
            *(float*)(sm + XD_B + prv*XBUF + xoff) = xpre;

        q_bar(barid);
    }

    __syncthreads();
    // ===== final FC + sigmoid: h2[511] in buf 1 =====
    if (tid < nb) {
        const int row = tid;
        int qq = 0;
        #pragma unroll
        for (int k = 1; k < 4; ++k)
            if (((k * nb) >> 2) <= row) qq = k;
        const int rl = row - ((qq * nb) >> 2);
        const char* h2f = sm + H2_B + HBUF + qq*768 + (rl >> 1)*384 + (rl & 1)*16;
        float acc = fcb[0];
        #pragma unroll
        for (int jj = 0; jj < HH; ++jj)
            acc = fmaf(*(const float*)(h2f + (jj >> 2)*32 + (jj & 3)*4), fcw[jj], acc);
        out[rs + row] = fsig(acc);
    }
}

extern "C" void kernel_launch(void* const* d_in, const int* in_sizes, int n_in,
                              void* d_out, int out_size) {
    (void)in_sizes; (void)n_in; (void)out_size;
    cudaFuncSetAttribute(lstm2_kernel,
                         cudaFuncAttributeMaxDynamicSharedMemorySize, SMEM_BYTES);
    lstm2_kernel<<<NCTA, NTHREADS, SMEM_BYTES>>>(
        (const float*)d_in[0],
        (const float*)d_in[1], (const float*)d_in[2],
        (const float*)d_in[3], (const float*)d_in[4],
        (const float*)d_in[5], (const float*)d_in[6],
        (const float*)d_in[7], (const float*)d_in[8],
        (const float*)d_in[9], (const float*)d_in[10],
        (float*)d_out);
}